// round 5
// baseline (speedup 1.0000x reference)
#include <cuda_runtime.h>
#include <cstdint>

// ExpertScatter: out[b, Ind[b,h,k], :] += Y[b,h,k,:] @ W[h]
// Y[8,16,1024,128] f32, Ind[8,16,1024] i32, W[16,128,1024] f32, out[8,4096,1024] f32
// R5: mma.sync tf32, 8 warps x (64x64) warp tile, swizzled fragment staging,
//     software-pipelined B staging, overlapped red.global.add.v2 epilogue.

#define BB 8
#define HH 16
#define KDIM 1024
#define DD 128
#define NN 1024
#define TT 4096

#define TM 256
#define TN 128
#define NCHUNK 8
#define THREADS 256
#define KS 16

#define AS_WORDS (TM * DD)   // 32768 u32 = 128KB
#define BS_WORDS (DD * TN)   // 16384 u32 = 64KB
#define SMEM_BYTES ((AS_WORDS + BS_WORDS) * 4)   // 196608

__global__ void zero_out_kernel(float4* __restrict__ p, int n4) {
    int i = blockIdx.x * blockDim.x + threadIdx.x;
    if (i < n4) p[i] = make_float4(0.f, 0.f, 0.f, 0.f);
}

__device__ __forceinline__ uint32_t f2tf32(float f) {
    uint32_t r; asm("cvt.rna.tf32.f32 %0, %1;" : "=r"(r) : "f"(f)); return r;
}
__device__ __forceinline__ void mma_tf32(float* c, const uint4 a, const uint2 b) {
    asm volatile(
        "mma.sync.aligned.m16n8k8.row.col.f32.tf32.tf32.f32 "
        "{%0,%1,%2,%3}, {%4,%5,%6,%7}, {%8,%9}, {%0,%1,%2,%3};"
        : "+f"(c[0]), "+f"(c[1]), "+f"(c[2]), "+f"(c[3])
        : "r"(a.x), "r"(a.y), "r"(a.z), "r"(a.w), "r"(b.x), "r"(b.y));
}
__device__ __forceinline__ void red_v2(float* p, float x, float y) {
    asm volatile("red.global.add.v2.f32 [%0], {%1, %2};"
                 :: "l"(p), "f"(x), "f"(y) : "memory");
}

// store one staged B float4 (4 n-values at (k, n4*4..+3)) into fragment layout
__device__ __forceinline__ void stage_b4(uint32_t* Bs, int k, int n4, float4 v) {
    const int ks  = k >> 3;
    const int kk  = k & 7;
    const int tg  = kk & 3;
    const int sel = kk >> 2;
    const uint32_t sz = (uint32_t)((ks & 3) << 2);
    const float vv[4] = { v.x, v.y, v.z, v.w };
    #pragma unroll
    for (int e = 0; e < 4; e++) {
        const int n  = n4 * 4 + e;
        const int nt = n >> 3;
        const int gg = n & 7;
        const uint32_t slot = (uint32_t)((gg << 2) + tg) ^ sz;
        Bs[((uint32_t)(nt * 16 + ks) * 32 + slot) * 2 + sel] = f2tf32(vv[e]);
    }
}

__global__ void __launch_bounds__(THREADS, 1)
expert_scatter_tc(const float* __restrict__ Y,
                  const int*   __restrict__ Ind,
                  const float* __restrict__ W,
                  float*       __restrict__ out) {
    const int b  = blockIdx.z;
    const int h  = blockIdx.y;
    const int k0 = blockIdx.x * TM;

    extern __shared__ uint32_t sm[];
    uint32_t* As = sm;
    uint32_t* Bs = sm + AS_WORDS;
    __shared__ int sInd[TM];

    const int tid  = threadIdx.x;
    const int warp = tid >> 5;
    const int lane = tid & 31;
    const int g    = lane >> 2;
    const int tig  = lane & 3;
    const int wm   = warp >> 1;   // 0..3 : 64-row band
    const int wn   = warp & 1;    // 0..1 : 64-col band

    // ---- Stage A: Y tile [256m x 128k] -> tf32 fragments, ks-swizzled ----
    const float* Yp = Y + ((size_t)(b * HH + h) * KDIM + k0) * DD;
    #pragma unroll
    for (int i = 0; i < 32; i++) {
        const int flat = i * THREADS + tid;
        const int m  = flat >> 5;
        const int k4 = flat & 31;
        const float4 v = *(const float4*)(Yp + (size_t)m * DD + k4 * 4);
        const int tile16 = m >> 4;
        const int r   = m & 15;
        const int gg  = r & 7;
        const int hi  = r >> 3;
        const int ks  = k4 >> 1;
        const int sel = k4 & 1;
        const int comp = hi + (sel << 1);
        const uint32_t base = ((uint32_t)(tile16 * 16 + ks)) * 32;
        const uint32_t sz = (uint32_t)(ks & 7);
        uint32_t wv[4] = { f2tf32(v.x), f2tf32(v.y), f2tf32(v.z), f2tf32(v.w) };
        #pragma unroll
        for (int e = 0; e < 4; e++) {
            const uint32_t slot = (uint32_t)((gg << 2) + e) ^ sz;
            As[(base + slot) * 4 + comp] = wv[e];
        }
    }
    sInd[tid] = Ind[(size_t)(b * HH + h) * KDIM + k0 + tid];

    const float* Wh  = W + (size_t)h * DD * NN;
    float* outb = out + (size_t)b * TT * NN;

    // ---- Prologue: stage full B chunk 0 ----
    #pragma unroll
    for (int i = 0; i < 16; i++) {
        const int flat = i * THREADS + tid;
        const int klo  = flat & 31;
        const int rest = flat >> 5;
        const int n4   = rest & 31;
        const int khi  = rest >> 5;
        const int k    = khi * 32 + klo;
        const float4 v = *(const float4*)(Wh + (size_t)k * NN + n4 * 4);
        stage_b4(Bs, k, n4, v);
    }
    __syncthreads();

    // per-warp scatter row indices
    int t0s[4], t1s[4];
    #pragma unroll
    for (int im = 0; im < 4; im++) {
        const int mrow = wm * 64 + im * 16;
        t0s[im] = sInd[mrow + g];
        t1s[im] = sInd[mrow + g + 8];
    }

    #pragma unroll 1
    for (int nc = 0; nc < NCHUNK; nc++) {
        // ---- Compute: warp tile 64m x 64n = 4(im) x 8(in) x 16(ks) ----
        float acc[4][8][4];
        #pragma unroll
        for (int im = 0; im < 4; im++)
            #pragma unroll
            for (int in = 0; in < 8; in++)
                #pragma unroll
                for (int c = 0; c < 4; c++) acc[im][in][c] = 0.f;

        const uint4* Af = (const uint4*)As;
        const uint2* Bf = (const uint2*)Bs;
        #pragma unroll
        for (int ks = 0; ks < KS; ks++) {
            const int laneA = lane ^ (ks & 7);
            const int laneB = lane ^ ((ks & 3) << 2);
            uint4 a[4];
            #pragma unroll
            for (int im = 0; im < 4; im++)
                a[im] = Af[((wm * 4 + im) * 16 + ks) * 32 + laneA];
            #pragma unroll
            for (int in = 0; in < 8; in++) {
                const uint2 bf = Bf[((wn * 8 + in) * 16 + ks) * 32 + laneB];
                #pragma unroll
                for (int im = 0; im < 4; im++)
                    mma_tf32(acc[im][in], a[im], bf);
            }
        }

        // ---- Prefetch first half (k<64) of next B chunk into registers ----
        float4 pf[8];
        if (nc < NCHUNK - 1) {
            const float* Wn = Wh + (size_t)(nc + 1) * TN;
            #pragma unroll
            for (int i = 0; i < 8; i++) {
                const int flat = i * THREADS + tid;
                const int klo  = flat & 31;
                const int rest = flat >> 5;
                const int n4   = rest & 31;
                const int khi  = rest >> 5;      // 0..1
                const int k    = khi * 32 + klo;
                pf[i] = *(const float4*)(Wn + (size_t)k * NN + n4 * 4);
            }
        }
        __syncthreads();   // all warps done reading Bs

        if (nc < NCHUNK - 1) {
            const float* Wn = Wh + (size_t)(nc + 1) * TN;
            #pragma unroll
            for (int i = 0; i < 8; i++) {
                const int flat = i * THREADS + tid;
                const int klo  = flat & 31;
                const int rest = flat >> 5;
                const int n4   = rest & 31;
                const int khi  = rest >> 5;
                stage_b4(Bs, khi * 32 + klo, n4, pf[i]);
            }
            // second half (k >= 64): load + store, MLP across 8 iters
            #pragma unroll
            for (int i = 8; i < 16; i++) {
                const int flat = i * THREADS + tid;
                const int klo  = flat & 31;
                const int rest = flat >> 5;
                const int n4   = rest & 31;
                const int khi  = rest >> 5;      // 2..3
                const int k    = khi * 32 + klo;
                const float4 v = *(const float4*)(Wn + (size_t)k * NN + n4 * 4);
                stage_b4(Bs, k, n4, v);
            }
        }
        __syncthreads();   // Bs(nc+1) ready

        // ---- Epilogue for chunk nc (overlaps next chunk's MMA on other warps) ----
        const int colb = nc * TN + wn * 64 + tig * 2;
        #pragma unroll
        for (int im = 0; im < 4; im++) {
            float* r0 = outb + (size_t)t0s[im] * NN + colb;
            float* r1 = outb + (size_t)t1s[im] * NN + colb;
            #pragma unroll
            for (int in = 0; in < 8; in++) {
                red_v2(r0 + in * 8, acc[im][in][0], acc[im][in][1]);
                red_v2(r1 + in * 8, acc[im][in][2], acc[im][in][3]);
            }
        }
    }
}

extern "C" void kernel_launch(void* const* d_in, const int* in_sizes, int n_in,
                              void* d_out, int out_size) {
    const float* Y   = (const float*)d_in[0];
    const int*   Ind = (const int*)d_in[1];
    const float* W   = (const float*)d_in[n_in - 1];
    float* out = (float*)d_out;

    const int n4 = (BB * TT * NN) / 4;
    zero_out_kernel<<<(n4 + 511) / 512, 512>>>((float4*)out, n4);

    cudaFuncSetAttribute(expert_scatter_tc,
                         cudaFuncAttributeMaxDynamicSharedMemorySize, SMEM_BYTES);
    dim3 grid(KDIM / TM, HH, BB);   // 4 x 16 x 8 = 512 CTAs
    expert_scatter_tc<<<grid, THREADS, SMEM_BYTES>>>(Y, Ind, W, out);
}

// round 6
// speedup vs baseline: 1.5909x; 1.5909x over previous
#include <cuda_runtime.h>
#include <cuda_fp16.h>
#include <cstdint>

// ExpertScatter: out[b, Ind[b,h,k], :] += Y[b,h,k,:] @ W[h]
// Y[8,16,1024,128] f32, Ind[8,16,1024] i32, W[16,128,1024] f32, out[8,4096,1024] f32
// R6: fp16 m16n8k16 mma (same 10-bit mantissa as tf32), ldmatrix fragment loads,
//     native-layout B (LDSM.T), double-buffered B with reg prefetch, REDG.v2.

#define BB 8
#define HH 16
#define KDIM 1024
#define DD 128
#define NN 1024
#define TT 4096

#define TM 256
#define TN 128
#define NCHUNK 8
#define THREADS 512

#define AS_BYTES (TM * DD * 2)          // 65536: [m][k] halves, 16B chunks XOR-swizzled
#define BS_BYTES (DD * TN * 2)          // 32768: [k][n] halves, 16B chunks XOR-swizzled
#define SMEM_BYTES (AS_BYTES + 2 * BS_BYTES)   // 131072

__global__ void zero_out_kernel(float4* __restrict__ p, int n4) {
    int i = blockIdx.x * blockDim.x + threadIdx.x;
    if (i < n4) p[i] = make_float4(0.f, 0.f, 0.f, 0.f);
}

__device__ __forceinline__ uint32_t smem_u32(const void* p) {
    uint32_t a;
    asm("{ .reg .u64 t; cvta.to.shared.u64 t, %1; cvt.u32.u64 %0, t; }" : "=r"(a) : "l"(p));
    return a;
}
__device__ __forceinline__ uint32_t pack_h2(float a, float b) {
    __half2 h = __floats2half2_rn(a, b);
    return *(uint32_t*)&h;
}
__device__ __forceinline__ void ldsm_x4(uint32_t* r, uint32_t addr) {
    asm volatile("ldmatrix.sync.aligned.m8n8.x4.shared.b16 {%0,%1,%2,%3}, [%4];"
                 : "=r"(r[0]), "=r"(r[1]), "=r"(r[2]), "=r"(r[3]) : "r"(addr));
}
__device__ __forceinline__ void ldsm_x4_t(uint32_t* r, uint32_t addr) {
    asm volatile("ldmatrix.sync.aligned.m8n8.x4.trans.shared.b16 {%0,%1,%2,%3}, [%4];"
                 : "=r"(r[0]), "=r"(r[1]), "=r"(r[2]), "=r"(r[3]) : "r"(addr));
}
__device__ __forceinline__ void mma_f16(float* c, const uint32_t* a, const uint32_t* b) {
    asm volatile(
        "mma.sync.aligned.m16n8k16.row.col.f32.f16.f16.f32 "
        "{%0,%1,%2,%3}, {%4,%5,%6,%7}, {%8,%9}, {%0,%1,%2,%3};"
        : "+f"(c[0]), "+f"(c[1]), "+f"(c[2]), "+f"(c[3])
        : "r"(a[0]), "r"(a[1]), "r"(a[2]), "r"(a[3]), "r"(b[0]), "r"(b[1]));
}
__device__ __forceinline__ void red_v2(float* p, float x, float y) {
    asm volatile("red.global.add.v2.f32 [%0], {%1, %2};"
                 :: "l"(p), "f"(x), "f"(y) : "memory");
}

__global__ void __launch_bounds__(THREADS, 1)
expert_scatter_f16(const float* __restrict__ Y,
                   const int*   __restrict__ Ind,
                   const float* __restrict__ W,
                   float*       __restrict__ out) {
    const int b  = blockIdx.z;
    const int h  = blockIdx.y;
    const int k0 = blockIdx.x * TM;

    extern __shared__ char sm[];
    char* As  = sm;
    char* Bs[2] = { sm + AS_BYTES, sm + AS_BYTES + BS_BYTES };
    __shared__ int sInd[TM];

    const int tid  = threadIdx.x;
    const int warp = tid >> 5;
    const int lane = tid & 31;
    const int g    = lane >> 2;
    const int tig  = lane & 3;
    const int wm   = warp >> 2;   // 0..3 : 64-row band
    const int wn   = warp & 3;    // 0..3 : 32-col band

    const uint32_t As_a = smem_u32(As);
    const uint32_t Bs_a[2] = { smem_u32(Bs[0]), smem_u32(Bs[1]) };

    // ---- Stage A: Y[256m x 128k] f32 -> fp16 [m][k], 16B chunks, c ^= m&7 ----
    const float* Yp = Y + ((size_t)(b * HH + h) * KDIM + k0) * DD;
    #pragma unroll
    for (int i = 0; i < 8; i++) {
        const int flat = i * THREADS + tid;
        const int m = flat >> 4;
        const int c = flat & 15;
        const float4 v0 = *(const float4*)(Yp + (size_t)m * DD + c * 8);
        const float4 v1 = *(const float4*)(Yp + (size_t)m * DD + c * 8 + 4);
        uint4 w = { pack_h2(v0.x, v0.y), pack_h2(v0.z, v0.w),
                    pack_h2(v1.x, v1.y), pack_h2(v1.z, v1.w) };
        *(uint4*)(As + m * 256 + ((c ^ (m & 7)) << 4)) = w;
    }
    if (tid < TM) sInd[tid] = Ind[(size_t)(b * HH + h) * KDIM + k0 + tid];

    const float* Wh = W + (size_t)h * DD * NN;
    float* outb = out + (size_t)b * TT * NN;

    // ---- Stage B chunk 0: W[128k][128n] f32 -> fp16 [k][n], c ^= k&7 ----
    #pragma unroll
    for (int i = 0; i < 4; i++) {
        const int flat = i * THREADS + tid;
        const int k = flat >> 4;
        const int c = flat & 15;
        const float4 v0 = *(const float4*)(Wh + (size_t)k * NN + c * 8);
        const float4 v1 = *(const float4*)(Wh + (size_t)k * NN + c * 8 + 4);
        uint4 w = { pack_h2(v0.x, v0.y), pack_h2(v0.z, v0.w),
                    pack_h2(v1.x, v1.y), pack_h2(v1.z, v1.w) };
        *(uint4*)(Bs[0] + k * 256 + ((c ^ (k & 7)) << 4)) = w;
    }
    __syncthreads();

    // per-warp scatter rows (fixed across chunks)
    int t0s[4], t1s[4];
    #pragma unroll
    for (int im = 0; im < 4; im++) {
        const int mrow = wm * 64 + im * 16;
        t0s[im] = sInd[mrow + g];
        t1s[im] = sInd[mrow + g + 8];
    }

    // precomputed ldmatrix lane addresses (kt-invariant parts)
    // A: m_l = wm*64 + im*16 + ((lane>>3)&1)*8 + (lane&7); c = kt*2 + (lane>>4)
    const int a_ml_base = wm * 64 + ((lane >> 3) & 1) * 8 + (lane & 7);
    const int a_chi     = lane >> 4;                      // c low bit
    // B: k_l = kt*16 + ((lane>>3)&1)*8 + (lane&7); c = wn*4 + inp*2 + (lane>>4)
    const int b_kl_base = ((lane >> 3) & 1) * 8 + (lane & 7);

    #pragma unroll 1
    for (int nc = 0; nc < NCHUNK; nc++) {
        const int buf = nc & 1;

        // ---- Prefetch+convert next B chunk into registers (hidden by compute) ----
        uint4 pf[4];
        if (nc + 1 < NCHUNK) {
            const float* Wn = Wh + (size_t)(nc + 1) * TN;
            #pragma unroll
            for (int i = 0; i < 4; i++) {
                const int flat = i * THREADS + tid;
                const int k = flat >> 4;
                const int c = flat & 15;
                const float4 v0 = *(const float4*)(Wn + (size_t)k * NN + c * 8);
                const float4 v1 = *(const float4*)(Wn + (size_t)k * NN + c * 8 + 4);
                pf[i].x = pack_h2(v0.x, v0.y); pf[i].y = pack_h2(v0.z, v0.w);
                pf[i].z = pack_h2(v1.x, v1.y); pf[i].w = pack_h2(v1.z, v1.w);
            }
        }

        // ---- Compute: warp tile 64m x 32n = 4(im) x 4(in) x 8(kt) ----
        float acc[4][4][4];
        #pragma unroll
        for (int im = 0; im < 4; im++)
            #pragma unroll
            for (int in = 0; in < 4; in++)
                #pragma unroll
                for (int c = 0; c < 4; c++) acc[im][in][c] = 0.f;

        #pragma unroll
        for (int kt = 0; kt < 8; kt++) {
            uint32_t a[4][4], bfr[2][4];
            #pragma unroll
            for (int im = 0; im < 4; im++) {
                const int ml = a_ml_base + im * 16;
                const int c  = kt * 2 + a_chi;
                ldsm_x4(a[im], As_a + ml * 256 + ((c ^ (ml & 7)) << 4));
            }
            #pragma unroll
            for (int inp = 0; inp < 2; inp++) {
                const int kl = kt * 16 + b_kl_base;
                const int c  = wn * 4 + inp * 2 + (lane >> 4);
                ldsm_x4_t(bfr[inp], Bs_a[buf] + kl * 256 + ((c ^ (kl & 7)) << 4));
            }
            #pragma unroll
            for (int in = 0; in < 4; in++) {
                const uint32_t bb[2] = { bfr[in >> 1][(in & 1) * 2],
                                         bfr[in >> 1][(in & 1) * 2 + 1] };
                #pragma unroll
                for (int im = 0; im < 4; im++)
                    mma_f16(acc[im][in], a[im], bb);
            }
        }

        // ---- Commit prefetched B to the other buffer ----
        if (nc + 1 < NCHUNK) {
            #pragma unroll
            for (int i = 0; i < 4; i++) {
                const int flat = i * THREADS + tid;
                const int k = flat >> 4;
                const int c = flat & 15;
                *(uint4*)(Bs[buf ^ 1] + k * 256 + ((c ^ (k & 7)) << 4)) = pf[i];
            }
        }

        // ---- Epilogue: vectorized scatter-add ----
        const int colb = nc * TN + wn * 32 + tig * 2;
        #pragma unroll
        for (int im = 0; im < 4; im++) {
            float* r0 = outb + (size_t)t0s[im] * NN + colb;
            float* r1 = outb + (size_t)t1s[im] * NN + colb;
            #pragma unroll
            for (int in = 0; in < 4; in++) {
                red_v2(r0 + in * 8, acc[im][in][0], acc[im][in][1]);
                red_v2(r1 + in * 8, acc[im][in][2], acc[im][in][3]);
            }
        }
        __syncthreads();
    }
}

extern "C" void kernel_launch(void* const* d_in, const int* in_sizes, int n_in,
                              void* d_out, int out_size) {
    const float* Y   = (const float*)d_in[0];
    const int*   Ind = (const int*)d_in[1];
    const float* W   = (const float*)d_in[n_in - 1];
    float* out = (float*)d_out;

    const int n4 = (BB * TT * NN) / 4;
    zero_out_kernel<<<(n4 + 511) / 512, 512>>>((float4*)out, n4);

    cudaFuncSetAttribute(expert_scatter_f16,
                         cudaFuncAttributeMaxDynamicSharedMemorySize, SMEM_BYTES);
    dim3 grid(KDIM / TM, HH, BB);   // 4 x 16 x 8 = 512 CTAs
    expert_scatter_f16<<<grid, THREADS, SMEM_BYTES>>>(Y, Ind, W, out);
}